// round 1
// baseline (speedup 1.0000x reference)
#include <cuda_runtime.h>
#include <cuda_bf16.h>
#include <math.h>
#include <float.h>

// ---------------- problem constants ----------------
#define B_   8
#define E_   256
#define N_   32
#define D_   512
#define RD_  768
#define R_   2000
#define L_   2
#define K_   8
#define M_   32
#define HEADS_ 8
#define DH_  64
#define HLLM_ 4096
#define BE_  (B_*E_)      // 2048
#define BM_  (B_*M_)      // 256

// ---------------- scratch (device globals; no allocation allowed) ----------------
__device__ float g_relproj[R_*D_];      // projected relation table [2000,512]
__device__ float g_inorm[R_];           // 1/max(||row||,1e-12)
__device__ float g_states[BE_*D_];      // edge states
__device__ float g_agg[BE_*D_];         // top-k mean aggregate
__device__ float g_tmp1[BE_*D_];        // v_proj(agg)
__device__ float g_attn[BE_*D_];        // out_proj(...)
__device__ float g_h[BE_*4*D_];         // FF hidden [2048,2048]
__device__ float g_ff[BE_*D_];
__device__ float g_q[M_*D_];
__device__ float g_k[BE_*D_];
__device__ float g_v[BE_*D_];
__device__ float g_mem[BM_*D_];         // cross-attn output (bmhd)
__device__ float g_memo[BM_*D_];        // after t_ow
__device__ float g_noedge[B_];          // 0 if row has no edges else 1

// ---------------- generic NT GEMM: C[M,N] = A[M,K] @ W[N,K]^T + bias, opt GELU ----------------
// 64x64 tile, K-tile 16, 256 threads, 4x4 per thread.
__global__ void gemm_nt(const float* __restrict__ A, const float* __restrict__ W,
                        const float* __restrict__ bias, float* __restrict__ C,
                        int Mr, int Nc, int Kd, int act)
{
    __shared__ float As[16][64+4];
    __shared__ float Ws[16][64+4];
    const int tx = threadIdx.x & 15;      // 0..15 (cols)
    const int ty = threadIdx.x >> 4;      // 0..15 (rows)
    const int row0 = blockIdx.y * 64;
    const int col0 = blockIdx.x * 64;
    float acc[4][4] = {};

    for (int k0 = 0; k0 < Kd; k0 += 16) {
        #pragma unroll
        for (int i = 0; i < 4; i++) {
            int idx = threadIdx.x + i * 256;     // 0..1023
            int m = idx >> 4;                    // 0..63
            int k = idx & 15;                    // 0..15
            int gr = row0 + m;
            int gc = col0 + m;
            As[k][m] = (gr < Mr) ? A[(size_t)gr * Kd + k0 + k] : 0.f;
            Ws[k][m] = (gc < Nc) ? W[(size_t)gc * Kd + k0 + k] : 0.f;
        }
        __syncthreads();
        #pragma unroll
        for (int kk = 0; kk < 16; kk++) {
            float a[4], b[4];
            #pragma unroll
            for (int i = 0; i < 4; i++) a[i] = As[kk][ty*4 + i];
            #pragma unroll
            for (int j = 0; j < 4; j++) b[j] = Ws[kk][tx*4 + j];
            #pragma unroll
            for (int i = 0; i < 4; i++)
                #pragma unroll
                for (int j = 0; j < 4; j++)
                    acc[i][j] += a[i] * b[j];
        }
        __syncthreads();
    }

    #pragma unroll
    for (int i = 0; i < 4; i++) {
        int gr = row0 + ty*4 + i;
        if (gr >= Mr) continue;
        #pragma unroll
        for (int j = 0; j < 4; j++) {
            int gc = col0 + tx*4 + j;
            if (gc >= Nc) continue;
            float v = acc[i][j] + bias[gc];
            if (act == 1) v = 0.5f * v * (1.f + erff(v * 0.70710678118654752f));
            C[(size_t)gr * Nc + gc] = v;
        }
    }
}

// ---------------- per-row inverse norm of g_relproj ----------------
__global__ void rownorm_kernel()
{
    int r = blockIdx.x;
    __shared__ float red[256];
    float ss = 0.f;
    for (int d = threadIdx.x; d < D_; d += 256) {
        float v = g_relproj[(size_t)r * D_ + d];
        ss += v * v;
    }
    red[threadIdx.x] = ss;
    __syncthreads();
    for (int s = 128; s; s >>= 1) {
        if (threadIdx.x < s) red[threadIdx.x] += red[threadIdx.x + s];
        __syncthreads();
    }
    if (threadIdx.x == 0)
        g_inorm[r] = 1.f / fmaxf(sqrtf(red[0]), 1e-12f);
}

// ---------------- fused: states gather, cosine sims, top-8, mean agg ----------------
// one block per edge (2048 blocks, 256 threads = 8 warps)
__global__ void sims_topk_agg(const int* __restrict__ eids, const int* __restrict__ nids)
{
    int be = blockIdx.x;
    __shared__ float rn[D_];
    __shared__ float sims[N_];
    __shared__ int   topid[K_];

    int eid = eids[be];
    float ei = g_inorm[eid];
    for (int d = threadIdx.x; d < D_; d += 256) {
        float v = g_relproj[(size_t)eid * D_ + d];
        g_states[(size_t)be * D_ + d] = v;   // states init = rel_vec
        rn[d] = v * ei;
    }
    __syncthreads();

    int warp = threadIdx.x >> 5, lane = threadIdx.x & 31;
    for (int n = warp; n < N_; n += 8) {
        int nid = nids[(size_t)be * N_ + n];
        const float* row = &g_relproj[(size_t)nid * D_];
        float s = 0.f;
        for (int d = lane; d < D_; d += 32) s += row[d] * rn[d];
        #pragma unroll
        for (int o = 16; o; o >>= 1) s += __shfl_down_sync(0xffffffffu, s, o);
        if (lane == 0) sims[n] = s * g_inorm[nid];
    }
    __syncthreads();

    if (threadIdx.x == 0) {
        unsigned used = 0;
        for (int j = 0; j < K_; j++) {
            float best = -FLT_MAX; int bi = 0;
            for (int n = 0; n < N_; n++) {
                if ((used >> n) & 1u) continue;
                if (sims[n] > best) { best = sims[n]; bi = n; }
            }
            used |= 1u << bi;
            topid[j] = nids[(size_t)be * N_ + bi];
        }
    }
    __syncthreads();

    for (int d = threadIdx.x; d < D_; d += 256) {
        float acc = 0.f;
        #pragma unroll
        for (int j = 0; j < K_; j++) acc += g_relproj[(size_t)topid[j] * D_ + d];
        g_agg[(size_t)be * D_ + d] = acc * (1.f / K_);
    }
}

// ---------------- residual + layernorm (+optional mask): states = LN(states+add)*mask ----------------
__global__ void add_ln_kernel(const float* __restrict__ add,
                              const float* __restrict__ gamma, const float* __restrict__ beta,
                              const float* __restrict__ mask)
{
    int r = blockIdx.x;            // 0..2047
    int t = threadIdx.x;           // 256 threads, each handles d=t and d=t+256
    __shared__ float red[256];
    float x0 = g_states[(size_t)r*D_ + t]       + add[(size_t)r*D_ + t];
    float x1 = g_states[(size_t)r*D_ + t + 256] + add[(size_t)r*D_ + t + 256];

    red[t] = x0 + x1;
    __syncthreads();
    for (int s = 128; s; s >>= 1) { if (t < s) red[t] += red[t+s]; __syncthreads(); }
    float mu = red[0] * (1.f / D_);
    __syncthreads();

    float d0 = x0 - mu, d1 = x1 - mu;
    red[t] = d0*d0 + d1*d1;
    __syncthreads();
    for (int s = 128; s; s >>= 1) { if (t < s) red[t] += red[t+s]; __syncthreads(); }
    float inv = rsqrtf(red[0] * (1.f / D_) + 1e-5f);

    float mf = mask ? mask[r] : 1.f;
    g_states[(size_t)r*D_ + t]       = (d0 * inv * gamma[t]     + beta[t])     * mf;
    g_states[(size_t)r*D_ + t + 256] = (d1 * inv * gamma[t+256] + beta[t+256]) * mf;
}

// ---------------- memory-token cross attention: one block per (b,m) ----------------
__global__ void mem_attn(const float* __restrict__ edge_mask)
{
    int b = blockIdx.x >> 5;       // /32
    int m = blockIdx.x & 31;
    __shared__ float qs[D_];
    __shared__ float sc[HEADS_][E_];

    for (int d = threadIdx.x; d < D_; d += 256) qs[d] = g_q[(size_t)m * D_ + d];
    __syncthreads();

    int h = threadIdx.x >> 5, lane = threadIdx.x & 31;
    const float* kb = &g_k[(size_t)b * E_ * D_];
    const float* vb = &g_v[(size_t)b * E_ * D_];
    const float* mk = &edge_mask[(size_t)b * E_];

    for (int e = 0; e < E_; e++) {
        const float* kr = kb + (size_t)e * D_ + h * DH_;
        float s = kr[lane] * qs[h*DH_ + lane] + kr[lane+32] * qs[h*DH_ + lane + 32];
        #pragma unroll
        for (int o = 16; o; o >>= 1) s += __shfl_down_sync(0xffffffffu, s, o);
        if (lane == 0)
            sc[h][e] = (mk[e] == 0.f) ? -FLT_MAX : s * 0.125f;  // 1/sqrt(64)
    }
    __syncwarp();

    // warp-local softmax over E
    float mx = -FLT_MAX;
    for (int e = lane; e < E_; e += 32) mx = fmaxf(mx, sc[h][e]);
    #pragma unroll
    for (int o = 16; o; o >>= 1) mx = fmaxf(mx, __shfl_xor_sync(0xffffffffu, mx, o));
    float sum = 0.f;
    for (int e = lane; e < E_; e += 32) {
        float w = expf(sc[h][e] - mx);
        sc[h][e] = w;
        sum += w;
    }
    #pragma unroll
    for (int o = 16; o; o >>= 1) sum += __shfl_xor_sync(0xffffffffu, sum, o);
    float invs = 1.f / sum;
    __syncwarp();

    float a0 = 0.f, a1 = 0.f;
    for (int e = 0; e < E_; e++) {
        float w = sc[h][e];
        const float* vr = vb + (size_t)e * D_ + h * DH_;
        a0 += w * vr[lane];
        a1 += w * vr[lane + 32];
    }
    size_t o = (size_t)(b * M_ + m) * D_ + h * DH_;
    g_mem[o + lane]      = a0 * invs;
    g_mem[o + lane + 32] = a1 * invs;
}

// ---------------- no-edge handling ----------------
__global__ void noedge_flags(const float* __restrict__ edge_mask)
{
    int b = blockIdx.x;
    __shared__ float red[256];
    red[threadIdx.x] = edge_mask[(size_t)b * E_ + threadIdx.x];
    __syncthreads();
    for (int s = 128; s; s >>= 1) { if (threadIdx.x < s) red[threadIdx.x] += red[threadIdx.x+s]; __syncthreads(); }
    if (threadIdx.x == 0) g_noedge[b] = (red[0] == 0.f) ? 0.f : 1.f;
}

__global__ void apply_noedge()
{
    int i = blockIdx.x * 256 + threadIdx.x;    // over BM_*D_ = 131072
    int b = i / (M_ * D_);
    g_memo[i] *= g_noedge[b];
}

// ---------------- host launch ----------------
static inline dim3 gemm_grid(int Mr, int Nc) { return dim3((Nc + 63) / 64, (Mr + 63) / 64); }

extern "C" void kernel_launch(void* const* d_in, const int* in_sizes, int n_in,
                              void* d_out, int out_size)
{
    const int*   edge_rel_ids = (const int*)  d_in[0];
    const int*   neigh_ids    = (const int*)  d_in[1];
    const float* edge_mask    = (const float*)d_in[2];
    const float* rel_emb      = (const float*)d_in[3];
    const float* rp_w         = (const float*)d_in[4];
    const float* rp_b         = (const float*)d_in[5];
    const float* ly_vw        = (const float*)d_in[6];
    const float* ly_vb        = (const float*)d_in[7];
    const float* ly_ow        = (const float*)d_in[8];
    const float* ly_ob        = (const float*)d_in[9];
    const float* ly_n1g       = (const float*)d_in[10];
    const float* ly_n1b       = (const float*)d_in[11];
    const float* ly_n2g       = (const float*)d_in[12];
    const float* ly_n2b       = (const float*)d_in[13];
    const float* ly_w1        = (const float*)d_in[14];
    const float* ly_b1        = (const float*)d_in[15];
    const float* ly_w2        = (const float*)d_in[16];
    const float* ly_b2        = (const float*)d_in[17];
    const float* mem_q        = (const float*)d_in[18];
    const float* t_qw         = (const float*)d_in[19];
    const float* t_qb         = (const float*)d_in[20];
    const float* t_kw         = (const float*)d_in[21];
    const float* t_kb         = (const float*)d_in[22];
    const float* t_vw         = (const float*)d_in[23];
    const float* t_vb         = (const float*)d_in[24];
    const float* t_ow         = (const float*)d_in[25];
    const float* t_ob         = (const float*)d_in[26];
    const float* proj_w       = (const float*)d_in[27];
    const float* proj_b       = (const float*)d_in[28];
    float* out = (float*)d_out;

    float *p_relproj, *p_states, *p_agg, *p_tmp1, *p_attn, *p_h, *p_ff;
    float *p_q, *p_k, *p_v, *p_mem, *p_memo;
    cudaGetSymbolAddress((void**)&p_relproj, g_relproj);
    cudaGetSymbolAddress((void**)&p_states,  g_states);
    cudaGetSymbolAddress((void**)&p_agg,     g_agg);
    cudaGetSymbolAddress((void**)&p_tmp1,    g_tmp1);
    cudaGetSymbolAddress((void**)&p_attn,    g_attn);
    cudaGetSymbolAddress((void**)&p_h,       g_h);
    cudaGetSymbolAddress((void**)&p_ff,      g_ff);
    cudaGetSymbolAddress((void**)&p_q,       g_q);
    cudaGetSymbolAddress((void**)&p_k,       g_k);
    cudaGetSymbolAddress((void**)&p_v,       g_v);
    cudaGetSymbolAddress((void**)&p_mem,     g_mem);
    cudaGetSymbolAddress((void**)&p_memo,    g_memo);

    // 1) project entire relation table once (dedup of the dominant gather-GEMM)
    gemm_nt<<<gemm_grid(R_, D_), 256>>>(rel_emb, rp_w, rp_b, p_relproj, R_, D_, RD_, 0);
    rownorm_kernel<<<R_, 256>>>();

    // 2) fused cosine sims / top-8 / mean agg; also initializes states = rel_vec
    sims_topk_agg<<<BE_, 256>>>(edge_rel_ids, neigh_ids);

    // 3) relation-context layers
    for (int l = 0; l < L_; l++) {
        const float* vw = ly_vw + (size_t)l * D_ * D_;
        const float* vb = ly_vb + (size_t)l * D_;
        const float* ow = ly_ow + (size_t)l * D_ * D_;
        const float* ob = ly_ob + (size_t)l * D_;
        const float* w1 = ly_w1 + (size_t)l * 4 * D_ * D_;
        const float* b1 = ly_b1 + (size_t)l * 4 * D_;
        const float* w2 = ly_w2 + (size_t)l * D_ * 4 * D_;
        const float* b2 = ly_b2 + (size_t)l * D_;

        gemm_nt<<<gemm_grid(BE_, D_), 256>>>(p_agg,  vw, vb, p_tmp1, BE_, D_, D_, 0);
        gemm_nt<<<gemm_grid(BE_, D_), 256>>>(p_tmp1, ow, ob, p_attn, BE_, D_, D_, 0);
        add_ln_kernel<<<BE_, 256>>>(p_attn, ly_n1g + (size_t)l*D_, ly_n1b + (size_t)l*D_, nullptr);
        gemm_nt<<<gemm_grid(BE_, 4*D_), 256>>>(p_states, w1, b1, p_h, BE_, 4*D_, D_, 1);
        gemm_nt<<<gemm_grid(BE_, D_), 256>>>(p_h, w2, b2, p_ff, BE_, D_, 4*D_, 0);
        add_ln_kernel<<<BE_, 256>>>(p_ff, ly_n2g + (size_t)l*D_, ly_n2b + (size_t)l*D_, edge_mask);
    }

    // 4) memory tokenizer
    gemm_nt<<<gemm_grid(M_, D_), 256>>>(mem_q, t_qw, t_qb, p_q, M_, D_, D_, 0);
    gemm_nt<<<gemm_grid(BE_, D_), 256>>>(p_states, t_kw, t_kb, p_k, BE_, D_, D_, 0);
    gemm_nt<<<gemm_grid(BE_, D_), 256>>>(p_states, t_vw, t_vb, p_v, BE_, D_, D_, 0);
    mem_attn<<<BM_, 256>>>(edge_mask);
    gemm_nt<<<gemm_grid(BM_, D_), 256>>>(p_mem, t_ow, t_ob, p_memo, BM_, D_, D_, 0);
    noedge_flags<<<B_, 256>>>(edge_mask);
    apply_noedge<<<(BM_*D_)/256, 256>>>();

    // 5) final projection to LLM hidden size
    gemm_nt<<<gemm_grid(BM_, HLLM_), 256>>>(p_memo, proj_w, proj_b, out, BM_, HLLM_, D_, 0);
}

// round 2
// speedup vs baseline: 1.0819x; 1.0819x over previous
#include <cuda_runtime.h>
#include <cuda_bf16.h>
#include <math.h>
#include <float.h>

// ---------------- problem constants ----------------
#define B_   8
#define E_   256
#define N_   32
#define D_   512
#define RD_  768
#define R_   2000
#define L_   2
#define K_   8
#define M_   32
#define HEADS_ 8
#define DH_  64
#define HLLM_ 4096
#define BE_  (B_*E_)      // 2048
#define BM_  (B_*M_)      // 256

// ---------------- scratch (device globals; no allocation allowed) ----------------
__device__ float g_relproj[R_*D_];      // projected relation table [2000,512]
__device__ float g_inorm[R_];           // 1/max(||row||,1e-12)
__device__ float g_states[BE_*D_];      // edge states
__device__ float g_agg[BE_*D_];         // top-k mean aggregate
__device__ float g_tmp1[BE_*D_];        // v_proj(agg)
__device__ float g_attn[BE_*D_];        // out_proj(...)
__device__ float g_h[BE_*4*D_];         // FF hidden [2048,2048]
__device__ float g_ff[BE_*D_];
__device__ float g_q[M_*D_];
__device__ float g_k[BE_*D_];
__device__ float g_v[BE_*D_];
__device__ float g_mem[BM_*D_];         // cross-attn output (bmhd)
__device__ float g_memo[BM_*D_];        // after t_ow
__device__ float g_noedge[B_];          // 0 if row has no edges else 1

// ---------------- register-blocked NT GEMM ----------------
// C[M,N] = A[M,K] @ W[N,K]^T + bias, optional exact GELU.
// BM=128, BN=64, BK=16, 256 threads, 8x4 accumulators per thread.
// Requirements: Kd % 16 == 0, Nc % 64 == 0 (true for all shapes here); M guarded.
__global__ __launch_bounds__(256) void gemm_nt(
    const float* __restrict__ A, const float* __restrict__ W,
    const float* __restrict__ bias, float* __restrict__ C,
    int Mr, int Nc, int Kd, int act)
{
    __shared__ float As[16][132];   // [k][m], padded (132 % 4 == 0 keeps f4 reads aligned)
    __shared__ float Ws[16][68];    // [k][n]

    const int tid  = threadIdx.x;
    const int row0 = blockIdx.y * 128;
    const int col0 = blockIdx.x * 64;
    const int ty   = tid >> 4;        // 0..15 -> 8 rows each
    const int tx   = tid & 15;        // 0..15 -> 4 cols each

    const int lRow  = tid >> 2;       // 0..63
    const int lCol4 = (tid & 3) * 4;  // 0,4,8,12

    float acc[8][4] = {};

    for (int k0 = 0; k0 < Kd; k0 += 16) {
        // load A tile: rows lRow and lRow+64, 4 k's each (float4)
        #pragma unroll
        for (int i = 0; i < 2; i++) {
            int r  = lRow + i * 64;
            int gr = row0 + r;
            float4 v = make_float4(0.f, 0.f, 0.f, 0.f);
            if (gr < Mr) v = *(const float4*)&A[(size_t)gr * Kd + k0 + lCol4];
            As[lCol4 + 0][r] = v.x;
            As[lCol4 + 1][r] = v.y;
            As[lCol4 + 2][r] = v.z;
            As[lCol4 + 3][r] = v.w;
        }
        // load W tile: row (=output col) lRow, 4 k's (float4)
        {
            int gc = col0 + lRow;
            float4 v = make_float4(0.f, 0.f, 0.f, 0.f);
            if (gc < Nc) v = *(const float4*)&W[(size_t)gc * Kd + k0 + lCol4];
            Ws[lCol4 + 0][lRow] = v.x;
            Ws[lCol4 + 1][lRow] = v.y;
            Ws[lCol4 + 2][lRow] = v.z;
            Ws[lCol4 + 3][lRow] = v.w;
        }
        __syncthreads();

        #pragma unroll
        for (int kk = 0; kk < 16; kk++) {
            float4 a0 = *(const float4*)&As[kk][ty * 8];
            float4 a1 = *(const float4*)&As[kk][ty * 8 + 4];
            float4 b  = *(const float4*)&Ws[kk][tx * 4];
            float av[8] = {a0.x, a0.y, a0.z, a0.w, a1.x, a1.y, a1.z, a1.w};
            float bv[4] = {b.x, b.y, b.z, b.w};
            #pragma unroll
            for (int i = 0; i < 8; i++)
                #pragma unroll
                for (int j = 0; j < 4; j++)
                    acc[i][j] += av[i] * bv[j];
        }
        __syncthreads();
    }

    // epilogue: bias (+GELU), vectorized stores
    const int gc = col0 + tx * 4;
    float4 bb = *(const float4*)&bias[gc];
    #pragma unroll
    for (int i = 0; i < 8; i++) {
        int gr = row0 + ty * 8 + i;
        if (gr >= Mr) continue;
        float4 o;
        o.x = acc[i][0] + bb.x;
        o.y = acc[i][1] + bb.y;
        o.z = acc[i][2] + bb.z;
        o.w = acc[i][3] + bb.w;
        if (act == 1) {
            o.x = 0.5f * o.x * (1.f + erff(o.x * 0.70710678118654752f));
            o.y = 0.5f * o.y * (1.f + erff(o.y * 0.70710678118654752f));
            o.z = 0.5f * o.z * (1.f + erff(o.z * 0.70710678118654752f));
            o.w = 0.5f * o.w * (1.f + erff(o.w * 0.70710678118654752f));
        }
        *(float4*)&C[(size_t)gr * Nc + gc] = o;
    }
}

// ---------------- per-row inverse norm of g_relproj ----------------
__global__ void rownorm_kernel()
{
    int r = blockIdx.x;
    __shared__ float red[256];
    float ss = 0.f;
    for (int d = threadIdx.x; d < D_; d += 256) {
        float v = g_relproj[(size_t)r * D_ + d];
        ss += v * v;
    }
    red[threadIdx.x] = ss;
    __syncthreads();
    for (int s = 128; s; s >>= 1) {
        if (threadIdx.x < s) red[threadIdx.x] += red[threadIdx.x + s];
        __syncthreads();
    }
    if (threadIdx.x == 0)
        g_inorm[r] = 1.f / fmaxf(sqrtf(red[0]), 1e-12f);
}

// ---------------- fused: states gather, cosine sims, top-8, mean agg ----------------
__global__ void sims_topk_agg(const int* __restrict__ eids, const int* __restrict__ nids)
{
    int be = blockIdx.x;
    __shared__ float rn[D_];
    __shared__ float sims[N_];
    __shared__ int   topid[K_];

    int eid = eids[be];
    float ei = g_inorm[eid];
    for (int d = threadIdx.x; d < D_; d += 256) {
        float v = g_relproj[(size_t)eid * D_ + d];
        g_states[(size_t)be * D_ + d] = v;   // states init = rel_vec
        rn[d] = v * ei;
    }
    __syncthreads();

    int warp = threadIdx.x >> 5, lane = threadIdx.x & 31;
    for (int n = warp; n < N_; n += 8) {
        int nid = nids[(size_t)be * N_ + n];
        const float* row = &g_relproj[(size_t)nid * D_];
        float s = 0.f;
        for (int d = lane; d < D_; d += 32) s += row[d] * rn[d];
        #pragma unroll
        for (int o = 16; o; o >>= 1) s += __shfl_down_sync(0xffffffffu, s, o);
        if (lane == 0) sims[n] = s * g_inorm[nid];
    }
    __syncthreads();

    if (threadIdx.x == 0) {
        unsigned used = 0;
        for (int j = 0; j < K_; j++) {
            float best = -FLT_MAX; int bi = 0;
            for (int n = 0; n < N_; n++) {
                if ((used >> n) & 1u) continue;
                if (sims[n] > best) { best = sims[n]; bi = n; }
            }
            used |= 1u << bi;
            topid[j] = nids[(size_t)be * N_ + bi];
        }
    }
    __syncthreads();

    for (int d = threadIdx.x; d < D_; d += 256) {
        float acc = 0.f;
        #pragma unroll
        for (int j = 0; j < K_; j++) acc += g_relproj[(size_t)topid[j] * D_ + d];
        g_agg[(size_t)be * D_ + d] = acc * (1.f / K_);
    }
}

// ---------------- residual + layernorm (+optional mask) ----------------
__global__ void add_ln_kernel(const float* __restrict__ add,
                              const float* __restrict__ gamma, const float* __restrict__ beta,
                              const float* __restrict__ mask)
{
    int r = blockIdx.x;
    int t = threadIdx.x;
    __shared__ float red[256];
    float x0 = g_states[(size_t)r*D_ + t]       + add[(size_t)r*D_ + t];
    float x1 = g_states[(size_t)r*D_ + t + 256] + add[(size_t)r*D_ + t + 256];

    red[t] = x0 + x1;
    __syncthreads();
    for (int s = 128; s; s >>= 1) { if (t < s) red[t] += red[t+s]; __syncthreads(); }
    float mu = red[0] * (1.f / D_);
    __syncthreads();

    float d0 = x0 - mu, d1 = x1 - mu;
    red[t] = d0*d0 + d1*d1;
    __syncthreads();
    for (int s = 128; s; s >>= 1) { if (t < s) red[t] += red[t+s]; __syncthreads(); }
    float inv = rsqrtf(red[0] * (1.f / D_) + 1e-5f);

    float mf = mask ? mask[r] : 1.f;
    g_states[(size_t)r*D_ + t]       = (d0 * inv * gamma[t]     + beta[t])     * mf;
    g_states[(size_t)r*D_ + t + 256] = (d1 * inv * gamma[t+256] + beta[t+256]) * mf;
}

// ---------------- memory-token cross attention: one block per (b,m) ----------------
__global__ void mem_attn(const float* __restrict__ edge_mask)
{
    int b = blockIdx.x >> 5;
    int m = blockIdx.x & 31;
    __shared__ float qs[D_];
    __shared__ float sc[HEADS_][E_];

    for (int d = threadIdx.x; d < D_; d += 256) qs[d] = g_q[(size_t)m * D_ + d];
    __syncthreads();

    int h = threadIdx.x >> 5, lane = threadIdx.x & 31;
    const float* kb = &g_k[(size_t)b * E_ * D_];
    const float* vb = &g_v[(size_t)b * E_ * D_];
    const float* mk = &edge_mask[(size_t)b * E_];

    for (int e = 0; e < E_; e++) {
        const float* kr = kb + (size_t)e * D_ + h * DH_;
        float s = kr[lane] * qs[h*DH_ + lane] + kr[lane+32] * qs[h*DH_ + lane + 32];
        #pragma unroll
        for (int o = 16; o; o >>= 1) s += __shfl_down_sync(0xffffffffu, s, o);
        if (lane == 0)
            sc[h][e] = (mk[e] == 0.f) ? -FLT_MAX : s * 0.125f;
    }
    __syncwarp();

    float mx = -FLT_MAX;
    for (int e = lane; e < E_; e += 32) mx = fmaxf(mx, sc[h][e]);
    #pragma unroll
    for (int o = 16; o; o >>= 1) mx = fmaxf(mx, __shfl_xor_sync(0xffffffffu, mx, o));
    float sum = 0.f;
    for (int e = lane; e < E_; e += 32) {
        float w = expf(sc[h][e] - mx);
        sc[h][e] = w;
        sum += w;
    }
    #pragma unroll
    for (int o = 16; o; o >>= 1) sum += __shfl_xor_sync(0xffffffffu, sum, o);
    float invs = 1.f / sum;
    __syncwarp();

    float a0 = 0.f, a1 = 0.f;
    for (int e = 0; e < E_; e++) {
        float w = sc[h][e];
        const float* vr = vb + (size_t)e * D_ + h * DH_;
        a0 += w * vr[lane];
        a1 += w * vr[lane + 32];
    }
    size_t o = (size_t)(b * M_ + m) * D_ + h * DH_;
    g_mem[o + lane]      = a0 * invs;
    g_mem[o + lane + 32] = a1 * invs;
}

// ---------------- no-edge handling ----------------
__global__ void noedge_flags(const float* __restrict__ edge_mask)
{
    int b = blockIdx.x;
    __shared__ float red[256];
    red[threadIdx.x] = edge_mask[(size_t)b * E_ + threadIdx.x];
    __syncthreads();
    for (int s = 128; s; s >>= 1) { if (threadIdx.x < s) red[threadIdx.x] += red[threadIdx.x+s]; __syncthreads(); }
    if (threadIdx.x == 0) g_noedge[b] = (red[0] == 0.f) ? 0.f : 1.f;
}

__global__ void apply_noedge()
{
    int i = blockIdx.x * 256 + threadIdx.x;
    int b = i / (M_ * D_);
    g_memo[i] *= g_noedge[b];
}

// ---------------- host launch ----------------
static inline dim3 gemm_grid(int Mr, int Nc) { return dim3((Nc + 63) / 64, (Mr + 127) / 128); }

extern "C" void kernel_launch(void* const* d_in, const int* in_sizes, int n_in,
                              void* d_out, int out_size)
{
    const int*   edge_rel_ids = (const int*)  d_in[0];
    const int*   neigh_ids    = (const int*)  d_in[1];
    const float* edge_mask    = (const float*)d_in[2];
    const float* rel_emb      = (const float*)d_in[3];
    const float* rp_w         = (const float*)d_in[4];
    const float* rp_b         = (const float*)d_in[5];
    const float* ly_vw        = (const float*)d_in[6];
    const float* ly_vb        = (const float*)d_in[7];
    const float* ly_ow        = (const float*)d_in[8];
    const float* ly_ob        = (const float*)d_in[9];
    const float* ly_n1g       = (const float*)d_in[10];
    const float* ly_n1b       = (const float*)d_in[11];
    const float* ly_n2g       = (const float*)d_in[12];
    const float* ly_n2b       = (const float*)d_in[13];
    const float* ly_w1        = (const float*)d_in[14];
    const float* ly_b1        = (const float*)d_in[15];
    const float* ly_w2        = (const float*)d_in[16];
    const float* ly_b2        = (const float*)d_in[17];
    const float* mem_q        = (const float*)d_in[18];
    const float* t_qw         = (const float*)d_in[19];
    const float* t_qb         = (const float*)d_in[20];
    const float* t_kw         = (const float*)d_in[21];
    const float* t_kb         = (const float*)d_in[22];
    const float* t_vw         = (const float*)d_in[23];
    const float* t_vb         = (const float*)d_in[24];
    const float* t_ow         = (const float*)d_in[25];
    const float* t_ob         = (const float*)d_in[26];
    const float* proj_w       = (const float*)d_in[27];
    const float* proj_b       = (const float*)d_in[28];
    float* out = (float*)d_out;

    float *p_relproj, *p_states, *p_agg, *p_tmp1, *p_attn, *p_h, *p_ff;
    float *p_q, *p_k, *p_v, *p_mem, *p_memo;
    cudaGetSymbolAddress((void**)&p_relproj, g_relproj);
    cudaGetSymbolAddress((void**)&p_states,  g_states);
    cudaGetSymbolAddress((void**)&p_agg,     g_agg);
    cudaGetSymbolAddress((void**)&p_tmp1,    g_tmp1);
    cudaGetSymbolAddress((void**)&p_attn,    g_attn);
    cudaGetSymbolAddress((void**)&p_h,       g_h);
    cudaGetSymbolAddress((void**)&p_ff,      g_ff);
    cudaGetSymbolAddress((void**)&p_q,       g_q);
    cudaGetSymbolAddress((void**)&p_k,       g_k);
    cudaGetSymbolAddress((void**)&p_v,       g_v);
    cudaGetSymbolAddress((void**)&p_mem,     g_mem);
    cudaGetSymbolAddress((void**)&p_memo,    g_memo);

    // 1) project entire relation table once
    gemm_nt<<<gemm_grid(R_, D_), 256>>>(rel_emb, rp_w, rp_b, p_relproj, R_, D_, RD_, 0);
    rownorm_kernel<<<R_, 256>>>();

    // 2) fused cosine sims / top-8 / mean agg; also initializes states = rel_vec
    sims_topk_agg<<<BE_, 256>>>(edge_rel_ids, neigh_ids);

    // 3) relation-context layers
    for (int l = 0; l < L_; l++) {
        const float* vw = ly_vw + (size_t)l * D_ * D_;
        const float* vb = ly_vb + (size_t)l * D_;
        const float* ow = ly_ow + (size_t)l * D_ * D_;
        const float* ob = ly_ob + (size_t)l * D_;
        const float* w1 = ly_w1 + (size_t)l * 4 * D_ * D_;
        const float* b1 = ly_b1 + (size_t)l * 4 * D_;
        const float* w2 = ly_w2 + (size_t)l * D_ * 4 * D_;
        const float* b2 = ly_b2 + (size_t)l * D_;

        gemm_nt<<<gemm_grid(BE_, D_), 256>>>(p_agg,  vw, vb, p_tmp1, BE_, D_, D_, 0);
        gemm_nt<<<gemm_grid(BE_, D_), 256>>>(p_tmp1, ow, ob, p_attn, BE_, D_, D_, 0);
        add_ln_kernel<<<BE_, 256>>>(p_attn, ly_n1g + (size_t)l*D_, ly_n1b + (size_t)l*D_, nullptr);
        gemm_nt<<<gemm_grid(BE_, 4*D_), 256>>>(p_states, w1, b1, p_h, BE_, 4*D_, D_, 1);
        gemm_nt<<<gemm_grid(BE_, D_), 256>>>(p_h, w2, b2, p_ff, BE_, D_, 4*D_, 0);
        add_ln_kernel<<<BE_, 256>>>(p_ff, ly_n2g + (size_t)l*D_, ly_n2b + (size_t)l*D_, edge_mask);
    }

    // 4) memory tokenizer
    gemm_nt<<<gemm_grid(M_, D_), 256>>>(mem_q, t_qw, t_qb, p_q, M_, D_, D_, 0);
    gemm_nt<<<gemm_grid(BE_, D_), 256>>>(p_states, t_kw, t_kb, p_k, BE_, D_, D_, 0);
    gemm_nt<<<gemm_grid(BE_, D_), 256>>>(p_states, t_vw, t_vb, p_v, BE_, D_, D_, 0);
    mem_attn<<<BM_, 256>>>(edge_mask);
    gemm_nt<<<gemm_grid(BM_, D_), 256>>>(p_mem, t_ow, t_ob, p_memo, BM_, D_, D_, 0);
    noedge_flags<<<B_, 256>>>(edge_mask);
    apply_noedge<<<(BM_*D_)/256, 256>>>();

    // 5) final projection to LLM hidden size
    gemm_nt<<<gemm_grid(BM_, HLLM_), 256>>>(p_memo, proj_w, proj_b, out, BM_, HLLM_, D_, 0);
}

// round 3
// speedup vs baseline: 2.1358x; 1.9742x over previous
#include <cuda_runtime.h>
#include <cuda_bf16.h>
#include <math.h>
#include <float.h>

// ---------------- problem constants ----------------
#define B_   8
#define E_   256
#define N_   32
#define D_   512
#define RD_  768
#define R_   2000
#define L_   2
#define K_   8
#define M_   32
#define HEADS_ 8
#define DH_  64
#define HLLM_ 4096
#define BE_  (B_*E_)      // 2048
#define BM_  (B_*M_)      // 256

// ---------------- scratch (device globals; no allocation allowed) ----------------
__device__ float g_relproj[R_*D_];
__device__ float g_inorm[R_];
__device__ float g_states[BE_*D_];
__device__ float g_agg[BE_*D_];
__device__ float g_tmp1[BE_*D_];
__device__ float g_attn[BE_*D_];
__device__ float g_h[BE_*4*D_];
__device__ float g_ff[BE_*D_];
__device__ float g_q[M_*D_];
__device__ float g_k[BE_*D_];
__device__ float g_v[BE_*D_];
__device__ float g_mem[BM_*D_];
__device__ float g_memo[BM_*D_];
__device__ float g_noedge[B_];

// ---------------- tf32 helpers ----------------
__device__ __forceinline__ unsigned f2tf32(float f) {
    unsigned u;
    asm("cvt.rna.tf32.f32 %0, %1;" : "=r"(u) : "f"(f));
    return u;
}
__device__ __forceinline__ void mma_tf32(float c[4], const unsigned a[4], const unsigned b[2]) {
    asm volatile(
        "mma.sync.aligned.m16n8k8.row.col.f32.tf32.tf32.f32 "
        "{%0,%1,%2,%3}, {%4,%5,%6,%7}, {%8,%9}, {%0,%1,%2,%3};"
        : "+f"(c[0]), "+f"(c[1]), "+f"(c[2]), "+f"(c[3])
        : "r"(a[0]), "r"(a[1]), "r"(a[2]), "r"(a[3]), "r"(b[0]), "r"(b[1]));
}

// ---------------- tf32 tensor-core NT GEMM ----------------
// C[M,N] = A[M,K] @ W[N,K]^T + bias, optional exact GELU.
// CTA tile 128x64, BK=16, 256 threads (8 warps, 4x2), warp tile 32x32.
// Requirements: Kd % 16 == 0, Nc % 64 == 0 (all shapes here); M guarded.
__global__ __launch_bounds__(256) void gemm_tf32(
    const float* __restrict__ A, const float* __restrict__ W,
    const float* __restrict__ bias, float* __restrict__ C,
    int Mr, int Nc, int Kd, int act)
{
    __shared__ float As[2][128][20];   // [buf][m][k], stride 20 -> conflict-free frags
    __shared__ float Ws[2][64][20];    // [buf][n][k]

    const int tid  = threadIdx.x;
    const int warp = tid >> 5;
    const int lane = tid & 31;
    const int wy   = warp >> 1;        // 0..3 -> row offset wy*32
    const int wx   = warp & 1;         // 0..1 -> col offset wx*32
    const int grp  = lane >> 2;        // 0..7
    const int tig  = lane & 3;         // 0..3

    const int row0 = blockIdx.y * 128;
    const int col0 = blockIdx.x * 64;

    // global-load mapping
    const int am = tid >> 2;           // 0..63 (A rows am, am+64; W row am)
    const int ak = (tid & 3) * 4;      // k offset (float4)

    float acc[2][4][4] = {};

    const int nIter = Kd / 16;

    // ---- prologue: load tile 0 into buffer 0 ----
    {
        const int k0 = 0;
        float4 a0v = make_float4(0,0,0,0), a1v = make_float4(0,0,0,0);
        if (row0 + am      < Mr) a0v = *(const float4*)&A[(size_t)(row0+am)      * Kd + k0 + ak];
        if (row0 + am + 64 < Mr) a1v = *(const float4*)&A[(size_t)(row0+am+64)   * Kd + k0 + ak];
        float4 wv = *(const float4*)&W[(size_t)(col0+am) * Kd + k0 + ak];
        As[0][am][ak+0]    = __uint_as_float(f2tf32(a0v.x));
        As[0][am][ak+1]    = __uint_as_float(f2tf32(a0v.y));
        As[0][am][ak+2]    = __uint_as_float(f2tf32(a0v.z));
        As[0][am][ak+3]    = __uint_as_float(f2tf32(a0v.w));
        As[0][am+64][ak+0] = __uint_as_float(f2tf32(a1v.x));
        As[0][am+64][ak+1] = __uint_as_float(f2tf32(a1v.y));
        As[0][am+64][ak+2] = __uint_as_float(f2tf32(a1v.z));
        As[0][am+64][ak+3] = __uint_as_float(f2tf32(a1v.w));
        Ws[0][am][ak+0]    = __uint_as_float(f2tf32(wv.x));
        Ws[0][am][ak+1]    = __uint_as_float(f2tf32(wv.y));
        Ws[0][am][ak+2]    = __uint_as_float(f2tf32(wv.z));
        Ws[0][am][ak+3]    = __uint_as_float(f2tf32(wv.w));
    }
    __syncthreads();

    int buf = 0;
    for (int it = 0; it < nIter; it++) {
        // prefetch next k-tile into registers
        float4 a0v = make_float4(0,0,0,0), a1v = make_float4(0,0,0,0), wv = make_float4(0,0,0,0);
        const bool havenext = (it + 1 < nIter);
        if (havenext) {
            const int k0 = (it + 1) * 16;
            if (row0 + am      < Mr) a0v = *(const float4*)&A[(size_t)(row0+am)    * Kd + k0 + ak];
            if (row0 + am + 64 < Mr) a1v = *(const float4*)&A[(size_t)(row0+am+64) * Kd + k0 + ak];
            wv = *(const float4*)&W[(size_t)(col0+am) * Kd + k0 + ak];
        }

        // compute on current buffer: 2 k-steps of 8
        #pragma unroll
        for (int ks = 0; ks < 2; ks++) {
            const int kb = ks * 8;
            unsigned a[2][4];
            #pragma unroll
            for (int mt = 0; mt < 2; mt++) {
                const int mr = wy * 32 + mt * 16 + grp;
                a[mt][0] = __float_as_uint(As[buf][mr    ][kb + tig]);
                a[mt][1] = __float_as_uint(As[buf][mr + 8][kb + tig]);
                a[mt][2] = __float_as_uint(As[buf][mr    ][kb + tig + 4]);
                a[mt][3] = __float_as_uint(As[buf][mr + 8][kb + tig + 4]);
            }
            unsigned b[4][2];
            #pragma unroll
            for (int nt = 0; nt < 4; nt++) {
                const int nc = wx * 32 + nt * 8 + grp;
                b[nt][0] = __float_as_uint(Ws[buf][nc][kb + tig]);
                b[nt][1] = __float_as_uint(Ws[buf][nc][kb + tig + 4]);
            }
            #pragma unroll
            for (int mt = 0; mt < 2; mt++)
                #pragma unroll
                for (int nt = 0; nt < 4; nt++)
                    mma_tf32(acc[mt][nt], a[mt], b[nt]);
        }

        // store prefetched tile to the other buffer
        if (havenext) {
            const int nb = buf ^ 1;
            As[nb][am][ak+0]    = __uint_as_float(f2tf32(a0v.x));
            As[nb][am][ak+1]    = __uint_as_float(f2tf32(a0v.y));
            As[nb][am][ak+2]    = __uint_as_float(f2tf32(a0v.z));
            As[nb][am][ak+3]    = __uint_as_float(f2tf32(a0v.w));
            As[nb][am+64][ak+0] = __uint_as_float(f2tf32(a1v.x));
            As[nb][am+64][ak+1] = __uint_as_float(f2tf32(a1v.y));
            As[nb][am+64][ak+2] = __uint_as_float(f2tf32(a1v.z));
            As[nb][am+64][ak+3] = __uint_as_float(f2tf32(a1v.w));
            Ws[nb][am][ak+0]    = __uint_as_float(f2tf32(wv.x));
            Ws[nb][am][ak+1]    = __uint_as_float(f2tf32(wv.y));
            Ws[nb][am][ak+2]    = __uint_as_float(f2tf32(wv.z));
            Ws[nb][am][ak+3]    = __uint_as_float(f2tf32(wv.w));
        }
        __syncthreads();
        buf ^= 1;
    }

    // ---- epilogue ----
    #pragma unroll
    for (int mt = 0; mt < 2; mt++) {
        const int r0 = row0 + wy * 32 + mt * 16 + grp;
        const int r1 = r0 + 8;
        #pragma unroll
        for (int nt = 0; nt < 4; nt++) {
            const int gc = col0 + wx * 32 + nt * 8 + tig * 2;
            const float b0 = bias[gc], b1 = bias[gc + 1];
            float v0 = acc[mt][nt][0] + b0;
            float v1 = acc[mt][nt][1] + b1;
            float v2 = acc[mt][nt][2] + b0;
            float v3 = acc[mt][nt][3] + b1;
            if (act == 1) {
                v0 = 0.5f * v0 * (1.f + erff(v0 * 0.70710678118654752f));
                v1 = 0.5f * v1 * (1.f + erff(v1 * 0.70710678118654752f));
                v2 = 0.5f * v2 * (1.f + erff(v2 * 0.70710678118654752f));
                v3 = 0.5f * v3 * (1.f + erff(v3 * 0.70710678118654752f));
            }
            if (r0 < Mr) *(float2*)&C[(size_t)r0 * Nc + gc] = make_float2(v0, v1);
            if (r1 < Mr) *(float2*)&C[(size_t)r1 * Nc + gc] = make_float2(v2, v3);
        }
    }
}

// ---------------- fp32 SIMT NT GEMM (used only for the relation projection;
// its output feeds top-k selection, which must match fp32 ordering) ----------------
__global__ __launch_bounds__(256) void gemm_nt(
    const float* __restrict__ A, const float* __restrict__ W,
    const float* __restrict__ bias, float* __restrict__ C,
    int Mr, int Nc, int Kd, int act)
{
    __shared__ float As[16][132];
    __shared__ float Ws[16][68];

    const int tid  = threadIdx.x;
    const int row0 = blockIdx.y * 128;
    const int col0 = blockIdx.x * 64;
    const int ty   = tid >> 4;
    const int tx   = tid & 15;
    const int lRow  = tid >> 2;
    const int lCol4 = (tid & 3) * 4;

    float acc[8][4] = {};

    for (int k0 = 0; k0 < Kd; k0 += 16) {
        #pragma unroll
        for (int i = 0; i < 2; i++) {
            int r  = lRow + i * 64;
            int gr = row0 + r;
            float4 v = make_float4(0.f, 0.f, 0.f, 0.f);
            if (gr < Mr) v = *(const float4*)&A[(size_t)gr * Kd + k0 + lCol4];
            As[lCol4 + 0][r] = v.x; As[lCol4 + 1][r] = v.y;
            As[lCol4 + 2][r] = v.z; As[lCol4 + 3][r] = v.w;
        }
        {
            int gc = col0 + lRow;
            float4 v = make_float4(0.f, 0.f, 0.f, 0.f);
            if (gc < Nc) v = *(const float4*)&W[(size_t)gc * Kd + k0 + lCol4];
            Ws[lCol4 + 0][lRow] = v.x; Ws[lCol4 + 1][lRow] = v.y;
            Ws[lCol4 + 2][lRow] = v.z; Ws[lCol4 + 3][lRow] = v.w;
        }
        __syncthreads();

        #pragma unroll
        for (int kk = 0; kk < 16; kk++) {
            float4 a0 = *(const float4*)&As[kk][ty * 8];
            float4 a1 = *(const float4*)&As[kk][ty * 8 + 4];
            float4 b  = *(const float4*)&Ws[kk][tx * 4];
            float av[8] = {a0.x, a0.y, a0.z, a0.w, a1.x, a1.y, a1.z, a1.w};
            float bv[4] = {b.x, b.y, b.z, b.w};
            #pragma unroll
            for (int i = 0; i < 8; i++)
                #pragma unroll
                for (int j = 0; j < 4; j++)
                    acc[i][j] += av[i] * bv[j];
        }
        __syncthreads();
    }

    const int gc = col0 + tx * 4;
    float4 bb = *(const float4*)&bias[gc];
    #pragma unroll
    for (int i = 0; i < 8; i++) {
        int gr = row0 + ty * 8 + i;
        if (gr >= Mr) continue;
        float4 o;
        o.x = acc[i][0] + bb.x; o.y = acc[i][1] + bb.y;
        o.z = acc[i][2] + bb.z; o.w = acc[i][3] + bb.w;
        *(float4*)&C[(size_t)gr * Nc + gc] = o;
    }
    (void)act;
}

// ---------------- per-row inverse norm of g_relproj ----------------
__global__ void rownorm_kernel()
{
    int r = blockIdx.x;
    __shared__ float red[256];
    float ss = 0.f;
    for (int d = threadIdx.x; d < D_; d += 256) {
        float v = g_relproj[(size_t)r * D_ + d];
        ss += v * v;
    }
    red[threadIdx.x] = ss;
    __syncthreads();
    for (int s = 128; s; s >>= 1) {
        if (threadIdx.x < s) red[threadIdx.x] += red[threadIdx.x + s];
        __syncthreads();
    }
    if (threadIdx.x == 0)
        g_inorm[r] = 1.f / fmaxf(sqrtf(red[0]), 1e-12f);
}

// ---------------- fused: states gather, cosine sims, top-8, mean agg ----------------
__global__ void sims_topk_agg(const int* __restrict__ eids, const int* __restrict__ nids)
{
    int be = blockIdx.x;
    __shared__ float rn[D_];
    __shared__ float sims[N_];
    __shared__ int   topid[K_];

    int eid = eids[be];
    float ei = g_inorm[eid];
    for (int d = threadIdx.x; d < D_; d += 256) {
        float v = g_relproj[(size_t)eid * D_ + d];
        g_states[(size_t)be * D_ + d] = v;
        rn[d] = v * ei;
    }
    __syncthreads();

    int warp = threadIdx.x >> 5, lane = threadIdx.x & 31;
    for (int n = warp; n < N_; n += 8) {
        int nid = nids[(size_t)be * N_ + n];
        const float* row = &g_relproj[(size_t)nid * D_];
        float s = 0.f;
        for (int d = lane; d < D_; d += 32) s += row[d] * rn[d];
        #pragma unroll
        for (int o = 16; o; o >>= 1) s += __shfl_down_sync(0xffffffffu, s, o);
        if (lane == 0) sims[n] = s * g_inorm[nid];
    }
    __syncthreads();

    if (threadIdx.x == 0) {
        unsigned used = 0;
        for (int j = 0; j < K_; j++) {
            float best = -FLT_MAX; int bi = 0;
            for (int n = 0; n < N_; n++) {
                if ((used >> n) & 1u) continue;
                if (sims[n] > best) { best = sims[n]; bi = n; }
            }
            used |= 1u << bi;
            topid[j] = nids[(size_t)be * N_ + bi];
        }
    }
    __syncthreads();

    for (int d = threadIdx.x; d < D_; d += 256) {
        float acc = 0.f;
        #pragma unroll
        for (int j = 0; j < K_; j++) acc += g_relproj[(size_t)topid[j] * D_ + d];
        g_agg[(size_t)be * D_ + d] = acc * (1.f / K_);
    }
}

// ---------------- residual + layernorm (+optional mask) ----------------
__global__ void add_ln_kernel(const float* __restrict__ add,
                              const float* __restrict__ gamma, const float* __restrict__ beta,
                              const float* __restrict__ mask)
{
    int r = blockIdx.x;
    int t = threadIdx.x;
    __shared__ float red[256];
    float x0 = g_states[(size_t)r*D_ + t]       + add[(size_t)r*D_ + t];
    float x1 = g_states[(size_t)r*D_ + t + 256] + add[(size_t)r*D_ + t + 256];

    red[t] = x0 + x1;
    __syncthreads();
    for (int s = 128; s; s >>= 1) { if (t < s) red[t] += red[t+s]; __syncthreads(); }
    float mu = red[0] * (1.f / D_);
    __syncthreads();

    float d0 = x0 - mu, d1 = x1 - mu;
    red[t] = d0*d0 + d1*d1;
    __syncthreads();
    for (int s = 128; s; s >>= 1) { if (t < s) red[t] += red[t+s]; __syncthreads(); }
    float inv = rsqrtf(red[0] * (1.f / D_) + 1e-5f);

    float mf = mask ? mask[r] : 1.f;
    g_states[(size_t)r*D_ + t]       = (d0 * inv * gamma[t]     + beta[t])     * mf;
    g_states[(size_t)r*D_ + t + 256] = (d1 * inv * gamma[t+256] + beta[t+256]) * mf;
}

// ---------------- memory-token cross attention: one block per (b,m) ----------------
__global__ void mem_attn(const float* __restrict__ edge_mask)
{
    int b = blockIdx.x >> 5;
    int m = blockIdx.x & 31;
    __shared__ float qs[D_];
    __shared__ float sc[HEADS_][E_];

    for (int d = threadIdx.x; d < D_; d += 256) qs[d] = g_q[(size_t)m * D_ + d];
    __syncthreads();

    int h = threadIdx.x >> 5, lane = threadIdx.x & 31;
    const float* kb = &g_k[(size_t)b * E_ * D_];
    const float* vb = &g_v[(size_t)b * E_ * D_];
    const float* mk = &edge_mask[(size_t)b * E_];

    for (int e = 0; e < E_; e++) {
        const float* kr = kb + (size_t)e * D_ + h * DH_;
        float s = kr[lane] * qs[h*DH_ + lane] + kr[lane+32] * qs[h*DH_ + lane + 32];
        #pragma unroll
        for (int o = 16; o; o >>= 1) s += __shfl_down_sync(0xffffffffu, s, o);
        if (lane == 0)
            sc[h][e] = (mk[e] == 0.f) ? -FLT_MAX : s * 0.125f;
    }
    __syncwarp();

    float mx = -FLT_MAX;
    for (int e = lane; e < E_; e += 32) mx = fmaxf(mx, sc[h][e]);
    #pragma unroll
    for (int o = 16; o; o >>= 1) mx = fmaxf(mx, __shfl_xor_sync(0xffffffffu, mx, o));
    float sum = 0.f;
    for (int e = lane; e < E_; e += 32) {
        float w = expf(sc[h][e] - mx);
        sc[h][e] = w;
        sum += w;
    }
    #pragma unroll
    for (int o = 16; o; o >>= 1) sum += __shfl_xor_sync(0xffffffffu, sum, o);
    float invs = 1.f / sum;
    __syncwarp();

    float a0 = 0.f, a1 = 0.f;
    for (int e = 0; e < E_; e++) {
        float w = sc[h][e];
        const float* vr = vb + (size_t)e * D_ + h * DH_;
        a0 += w * vr[lane];
        a1 += w * vr[lane + 32];
    }
    size_t o = (size_t)(b * M_ + m) * D_ + h * DH_;
    g_mem[o + lane]      = a0 * invs;
    g_mem[o + lane + 32] = a1 * invs;
}

// ---------------- no-edge handling ----------------
__global__ void noedge_flags(const float* __restrict__ edge_mask)
{
    int b = blockIdx.x;
    __shared__ float red[256];
    red[threadIdx.x] = edge_mask[(size_t)b * E_ + threadIdx.x];
    __syncthreads();
    for (int s = 128; s; s >>= 1) { if (threadIdx.x < s) red[threadIdx.x] += red[threadIdx.x+s]; __syncthreads(); }
    if (threadIdx.x == 0) g_noedge[b] = (red[0] == 0.f) ? 0.f : 1.f;
}

__global__ void apply_noedge()
{
    int i = blockIdx.x * 256 + threadIdx.x;
    int b = i / (M_ * D_);
    g_memo[i] *= g_noedge[b];
}

// ---------------- host launch ----------------
static inline dim3 gemm_grid(int Mr, int Nc) { return dim3((Nc + 63) / 64, (Mr + 127) / 128); }

extern "C" void kernel_launch(void* const* d_in, const int* in_sizes, int n_in,
                              void* d_out, int out_size)
{
    const int*   edge_rel_ids = (const int*)  d_in[0];
    const int*   neigh_ids    = (const int*)  d_in[1];
    const float* edge_mask    = (const float*)d_in[2];
    const float* rel_emb      = (const float*)d_in[3];
    const float* rp_w         = (const float*)d_in[4];
    const float* rp_b         = (const float*)d_in[5];
    const float* ly_vw        = (const float*)d_in[6];
    const float* ly_vb        = (const float*)d_in[7];
    const float* ly_ow        = (const float*)d_in[8];
    const float* ly_ob        = (const float*)d_in[9];
    const float* ly_n1g       = (const float*)d_in[10];
    const float* ly_n1b       = (const float*)d_in[11];
    const float* ly_n2g       = (const float*)d_in[12];
    const float* ly_n2b       = (const float*)d_in[13];
    const float* ly_w1        = (const float*)d_in[14];
    const float* ly_b1        = (const float*)d_in[15];
    const float* ly_w2        = (const float*)d_in[16];
    const float* ly_b2        = (const float*)d_in[17];
    const float* mem_q        = (const float*)d_in[18];
    const float* t_qw         = (const float*)d_in[19];
    const float* t_qb         = (const float*)d_in[20];
    const float* t_kw         = (const float*)d_in[21];
    const float* t_kb         = (const float*)d_in[22];
    const float* t_vw         = (const float*)d_in[23];
    const float* t_vb         = (const float*)d_in[24];
    const float* t_ow         = (const float*)d_in[25];
    const float* t_ob         = (const float*)d_in[26];
    const float* proj_w       = (const float*)d_in[27];
    const float* proj_b       = (const float*)d_in[28];
    float* out = (float*)d_out;

    float *p_relproj, *p_states, *p_agg, *p_tmp1, *p_attn, *p_h, *p_ff;
    float *p_q, *p_k, *p_v, *p_mem, *p_memo;
    cudaGetSymbolAddress((void**)&p_relproj, g_relproj);
    cudaGetSymbolAddress((void**)&p_states,  g_states);
    cudaGetSymbolAddress((void**)&p_agg,     g_agg);
    cudaGetSymbolAddress((void**)&p_tmp1,    g_tmp1);
    cudaGetSymbolAddress((void**)&p_attn,    g_attn);
    cudaGetSymbolAddress((void**)&p_h,       g_h);
    cudaGetSymbolAddress((void**)&p_ff,      g_ff);
    cudaGetSymbolAddress((void**)&p_q,       g_q);
    cudaGetSymbolAddress((void**)&p_k,       g_k);
    cudaGetSymbolAddress((void**)&p_v,       g_v);
    cudaGetSymbolAddress((void**)&p_mem,     g_mem);
    cudaGetSymbolAddress((void**)&p_memo,    g_memo);

    // 1) project entire relation table once (fp32: feeds top-k ordering)
    gemm_nt<<<gemm_grid(R_, D_), 256>>>(rel_emb, rp_w, rp_b, p_relproj, R_, D_, RD_, 0);
    rownorm_kernel<<<R_, 256>>>();

    // 2) fused cosine sims / top-8 / mean agg; also initializes states = rel_vec
    sims_topk_agg<<<BE_, 256>>>(edge_rel_ids, neigh_ids);

    // 3) relation-context layers (tf32 tensor cores)
    for (int l = 0; l < L_; l++) {
        const float* vw = ly_vw + (size_t)l * D_ * D_;
        const float* vb = ly_vb + (size_t)l * D_;
        const float* ow = ly_ow + (size_t)l * D_ * D_;
        const float* ob = ly_ob + (size_t)l * D_;
        const float* w1 = ly_w1 + (size_t)l * 4 * D_ * D_;
        const float* b1 = ly_b1 + (size_t)l * 4 * D_;
        const float* w2 = ly_w2 + (size_t)l * D_ * 4 * D_;
        const float* b2 = ly_b2 + (size_t)l * D_;

        gemm_tf32<<<gemm_grid(BE_, D_), 256>>>(p_agg,  vw, vb, p_tmp1, BE_, D_, D_, 0);
        gemm_tf32<<<gemm_grid(BE_, D_), 256>>>(p_tmp1, ow, ob, p_attn, BE_, D_, D_, 0);
        add_ln_kernel<<<BE_, 256>>>(p_attn, ly_n1g + (size_t)l*D_, ly_n1b + (size_t)l*D_, nullptr);
        gemm_tf32<<<gemm_grid(BE_, 4*D_), 256>>>(p_states, w1, b1, p_h, BE_, 4*D_, D_, 1);
        gemm_tf32<<<gemm_grid(BE_, D_), 256>>>(p_h, w2, b2, p_ff, BE_, D_, 4*D_, 0);
        add_ln_kernel<<<BE_, 256>>>(p_ff, ly_n2g + (size_t)l*D_, ly_n2b + (size_t)l*D_, edge_mask);
    }

    // 4) memory tokenizer (tf32)
    gemm_tf32<<<gemm_grid(M_, D_), 256>>>(mem_q, t_qw, t_qb, p_q, M_, D_, D_, 0);
    gemm_tf32<<<gemm_grid(BE_, D_), 256>>>(p_states, t_kw, t_kb, p_k, BE_, D_, D_, 0);
    gemm_tf32<<<gemm_grid(BE_, D_), 256>>>(p_states, t_vw, t_vb, p_v, BE_, D_, D_, 0);
    mem_attn<<<BM_, 256>>>(edge_mask);
    gemm_tf32<<<gemm_grid(BM_, D_), 256>>>(p_mem, t_ow, t_ob, p_memo, BM_, D_, D_, 0);
    noedge_flags<<<B_, 256>>>(edge_mask);
    apply_noedge<<<(BM_*D_)/256, 256>>>();

    // 5) final projection to LLM hidden size (tf32)
    gemm_tf32<<<gemm_grid(BM_, HLLM_), 256>>>(p_memo, proj_w, proj_b, out, BM_, HLLM_, D_, 0);
}

// round 4
// speedup vs baseline: 2.5173x; 1.1786x over previous
#include <cuda_runtime.h>
#include <cuda_bf16.h>
#include <math.h>
#include <float.h>

// ---------------- problem constants ----------------
#define B_   8
#define E_   256
#define N_   32
#define D_   512
#define RD_  768
#define R_   2000
#define L_   2
#define K_   8
#define M_   32
#define HEADS_ 8
#define DH_  64
#define HLLM_ 4096
#define BE_  (B_*E_)      // 2048
#define BM_  (B_*M_)      // 256

// ---------------- scratch ----------------
__device__ float g_relproj[R_*D_];
__device__ float g_inorm[R_];
__device__ float g_states[BE_*D_];
__device__ float g_agg[BE_*D_];
__device__ float g_tmp1[BE_*D_];
__device__ float g_attn[BE_*D_];
__device__ float g_h[BE_*4*D_];
__device__ float g_ff[BE_*D_];
__device__ float g_q[M_*D_];
__device__ float g_k[BE_*D_];
__device__ float g_v[BE_*D_];
__device__ float g_mem[BM_*D_];
__device__ float g_memo[BM_*D_];
__device__ float g_noedge[B_];

// ---------------- tf32 helpers ----------------
__device__ __forceinline__ unsigned f2tf32(float f) {
    unsigned u;
    asm("cvt.rna.tf32.f32 %0, %1;" : "=r"(u) : "f"(f));
    return u;
}
__device__ __forceinline__ void mma_tf32(float c[4], const unsigned a[4], const unsigned b[2]) {
    asm volatile(
        "mma.sync.aligned.m16n8k8.row.col.f32.tf32.tf32.f32 "
        "{%0,%1,%2,%3}, {%4,%5,%6,%7}, {%8,%9}, {%0,%1,%2,%3};"
        : "+f"(c[0]), "+f"(c[1]), "+f"(c[2]), "+f"(c[3])
        : "r"(a[0]), "r"(a[1]), "r"(a[2]), "r"(a[3]), "r"(b[0]), "r"(b[1]));
}

__device__ __forceinline__ void stash4(float (*hi)[20], float (*lo)[20], bool split,
                                       int r, int ak, float4 v) {
    unsigned hx = f2tf32(v.x), hy = f2tf32(v.y), hz = f2tf32(v.z), hw = f2tf32(v.w);
    hi[r][ak+0] = __uint_as_float(hx);
    hi[r][ak+1] = __uint_as_float(hy);
    hi[r][ak+2] = __uint_as_float(hz);
    hi[r][ak+3] = __uint_as_float(hw);
    if (split) {
        lo[r][ak+0] = __uint_as_float(f2tf32(v.x - __uint_as_float(hx)));
        lo[r][ak+1] = __uint_as_float(f2tf32(v.y - __uint_as_float(hy)));
        lo[r][ak+2] = __uint_as_float(f2tf32(v.z - __uint_as_float(hz)));
        lo[r][ak+3] = __uint_as_float(f2tf32(v.w - __uint_as_float(hw)));
    }
}

// ---------------- tf32 tensor-core NT GEMM, 64x64 tile, 128 threads ----------------
// C[M,N] = A[M,K] @ W[N,K]^T + bias, optional exact GELU.
// SPLIT=true: Markidis 3-mma split for near-fp32 accuracy (used for relproj).
// blockIdx.z selects (W0,b0,C0) vs (W1,b1,C1) for batching independent GEMMs.
// Requirements: Kd % 16 == 0, Nc % 64 == 0; M guarded.
template<bool SPLIT>
__global__ __launch_bounds__(128) void gemm64(
    const float* __restrict__ A,
    const float* __restrict__ W0, const float* __restrict__ bias0, float* __restrict__ C0,
    const float* __restrict__ W1, const float* __restrict__ bias1, float* __restrict__ C1,
    int Mr, int Nc, int Kd, int act)
{
    constexpr int NS = SPLIT ? 2 : 1;
    __shared__ float As[2][NS][64][20];
    __shared__ float Ws[2][NS][64][20];

    const float* W    = blockIdx.z ? W1 : W0;
    const float* bias = blockIdx.z ? bias1 : bias0;
    float*       C    = blockIdx.z ? C1 : C0;

    const int tid  = threadIdx.x;
    const int warp = tid >> 5, lane = tid & 31;
    const int wy   = warp >> 1, wx = warp & 1;
    const int grp  = lane >> 2, tig = lane & 3;
    const int row0 = blockIdx.y * 64;
    const int col0 = blockIdx.x * 64;
    const int am   = tid >> 2;          // 0..31 -> rows am, am+32
    const int ak   = (tid & 3) * 4;

    float acc[2][4][4] = {};
    const int nIter = Kd / 16;

    // prologue: tile 0 -> buffer 0
    {
        float4 a0 = make_float4(0,0,0,0), a1 = make_float4(0,0,0,0);
        if (row0 + am      < Mr) a0 = *(const float4*)&A[(size_t)(row0+am)    * Kd + ak];
        if (row0 + am + 32 < Mr) a1 = *(const float4*)&A[(size_t)(row0+am+32) * Kd + ak];
        float4 w0 = *(const float4*)&W[(size_t)(col0+am)    * Kd + ak];
        float4 w1 = *(const float4*)&W[(size_t)(col0+am+32) * Kd + ak];
        stash4(As[0][0], As[0][NS-1], SPLIT, am,    ak, a0);
        stash4(As[0][0], As[0][NS-1], SPLIT, am+32, ak, a1);
        stash4(Ws[0][0], Ws[0][NS-1], SPLIT, am,    ak, w0);
        stash4(Ws[0][0], Ws[0][NS-1], SPLIT, am+32, ak, w1);
    }
    __syncthreads();

    int buf = 0;
    for (int it = 0; it < nIter; it++) {
        float4 a0 = make_float4(0,0,0,0), a1 = make_float4(0,0,0,0);
        float4 w0 = make_float4(0,0,0,0), w1 = make_float4(0,0,0,0);
        const bool havenext = (it + 1 < nIter);
        if (havenext) {
            const int k0 = (it + 1) * 16;
            if (row0 + am      < Mr) a0 = *(const float4*)&A[(size_t)(row0+am)    * Kd + k0 + ak];
            if (row0 + am + 32 < Mr) a1 = *(const float4*)&A[(size_t)(row0+am+32) * Kd + k0 + ak];
            w0 = *(const float4*)&W[(size_t)(col0+am)    * Kd + k0 + ak];
            w1 = *(const float4*)&W[(size_t)(col0+am+32) * Kd + k0 + ak];
        }

        #pragma unroll
        for (int ks = 0; ks < 2; ks++) {
            const int kb = ks * 8;
            unsigned aH[2][4], bH[4][2];
            unsigned aL[2][4], bL[4][2];
            #pragma unroll
            for (int mt = 0; mt < 2; mt++) {
                const int mr = wy * 32 + mt * 16 + grp;
                aH[mt][0] = __float_as_uint(As[buf][0][mr    ][kb + tig]);
                aH[mt][1] = __float_as_uint(As[buf][0][mr + 8][kb + tig]);
                aH[mt][2] = __float_as_uint(As[buf][0][mr    ][kb + tig + 4]);
                aH[mt][3] = __float_as_uint(As[buf][0][mr + 8][kb + tig + 4]);
                if (SPLIT) {
                    aL[mt][0] = __float_as_uint(As[buf][NS-1][mr    ][kb + tig]);
                    aL[mt][1] = __float_as_uint(As[buf][NS-1][mr + 8][kb + tig]);
                    aL[mt][2] = __float_as_uint(As[buf][NS-1][mr    ][kb + tig + 4]);
                    aL[mt][3] = __float_as_uint(As[buf][NS-1][mr + 8][kb + tig + 4]);
                }
            }
            #pragma unroll
            for (int nt = 0; nt < 4; nt++) {
                const int nc = wx * 32 + nt * 8 + grp;
                bH[nt][0] = __float_as_uint(Ws[buf][0][nc][kb + tig]);
                bH[nt][1] = __float_as_uint(Ws[buf][0][nc][kb + tig + 4]);
                if (SPLIT) {
                    bL[nt][0] = __float_as_uint(Ws[buf][NS-1][nc][kb + tig]);
                    bL[nt][1] = __float_as_uint(Ws[buf][NS-1][nc][kb + tig + 4]);
                }
            }
            #pragma unroll
            for (int mt = 0; mt < 2; mt++)
                #pragma unroll
                for (int nt = 0; nt < 4; nt++) {
                    mma_tf32(acc[mt][nt], aH[mt], bH[nt]);
                    if (SPLIT) {
                        mma_tf32(acc[mt][nt], aH[mt], bL[nt]);
                        mma_tf32(acc[mt][nt], aL[mt], bH[nt]);
                    }
                }
        }

        if (havenext) {
            const int nb = buf ^ 1;
            stash4(As[nb][0], As[nb][NS-1], SPLIT, am,    ak, a0);
            stash4(As[nb][0], As[nb][NS-1], SPLIT, am+32, ak, a1);
            stash4(Ws[nb][0], Ws[nb][NS-1], SPLIT, am,    ak, w0);
            stash4(Ws[nb][0], Ws[nb][NS-1], SPLIT, am+32, ak, w1);
        }
        __syncthreads();
        buf ^= 1;
    }

    // epilogue
    #pragma unroll
    for (int mt = 0; mt < 2; mt++) {
        const int r0 = row0 + wy * 32 + mt * 16 + grp;
        const int r1 = r0 + 8;
        #pragma unroll
        for (int nt = 0; nt < 4; nt++) {
            const int gc = col0 + wx * 32 + nt * 8 + tig * 2;
            const float b0 = bias[gc], b1 = bias[gc + 1];
            float v0 = acc[mt][nt][0] + b0;
            float v1 = acc[mt][nt][1] + b1;
            float v2 = acc[mt][nt][2] + b0;
            float v3 = acc[mt][nt][3] + b1;
            if (act == 1) {
                v0 = 0.5f * v0 * (1.f + erff(v0 * 0.70710678118654752f));
                v1 = 0.5f * v1 * (1.f + erff(v1 * 0.70710678118654752f));
                v2 = 0.5f * v2 * (1.f + erff(v2 * 0.70710678118654752f));
                v3 = 0.5f * v3 * (1.f + erff(v3 * 0.70710678118654752f));
            }
            if (r0 < Mr) *(float2*)&C[(size_t)r0 * Nc + gc] = make_float2(v0, v1);
            if (r1 < Mr) *(float2*)&C[(size_t)r1 * Nc + gc] = make_float2(v2, v3);
        }
    }
}

// ---------------- per-row inverse norm of g_relproj ----------------
__global__ void rownorm_kernel()
{
    int r = blockIdx.x;
    __shared__ float red[256];
    float ss = 0.f;
    for (int d = threadIdx.x; d < D_; d += 256) {
        float v = g_relproj[(size_t)r * D_ + d];
        ss += v * v;
    }
    red[threadIdx.x] = ss;
    __syncthreads();
    for (int s = 128; s; s >>= 1) {
        if (threadIdx.x < s) red[threadIdx.x] += red[threadIdx.x + s];
        __syncthreads();
    }
    if (threadIdx.x == 0)
        g_inorm[r] = 1.f / fmaxf(sqrtf(red[0]), 1e-12f);
}

// ---------------- fused: states gather, cosine sims, top-8, mean agg ----------------
__global__ void sims_topk_agg(const int* __restrict__ eids, const int* __restrict__ nids)
{
    int be = blockIdx.x;
    __shared__ float rn[D_];
    __shared__ float sims[N_];
    __shared__ int   topid[K_];

    int eid = eids[be];
    float ei = g_inorm[eid];
    for (int d = threadIdx.x; d < D_; d += 256) {
        float v = g_relproj[(size_t)eid * D_ + d];
        g_states[(size_t)be * D_ + d] = v;
        rn[d] = v * ei;
    }
    __syncthreads();

    int warp = threadIdx.x >> 5, lane = threadIdx.x & 31;
    for (int n = warp; n < N_; n += 8) {
        int nid = nids[(size_t)be * N_ + n];
        const float* row = &g_relproj[(size_t)nid * D_];
        float s = 0.f;
        for (int d = lane; d < D_; d += 32) s += row[d] * rn[d];
        #pragma unroll
        for (int o = 16; o; o >>= 1) s += __shfl_down_sync(0xffffffffu, s, o);
        if (lane == 0) sims[n] = s * g_inorm[nid];
    }
    __syncthreads();

    if (threadIdx.x == 0) {
        unsigned used = 0;
        for (int j = 0; j < K_; j++) {
            float best = -FLT_MAX; int bi = 0;
            for (int n = 0; n < N_; n++) {
                if ((used >> n) & 1u) continue;
                if (sims[n] > best) { best = sims[n]; bi = n; }
            }
            used |= 1u << bi;
            topid[j] = nids[(size_t)be * N_ + bi];
        }
    }
    __syncthreads();

    for (int d = threadIdx.x; d < D_; d += 256) {
        float acc = 0.f;
        #pragma unroll
        for (int j = 0; j < K_; j++) acc += g_relproj[(size_t)topid[j] * D_ + d];
        g_agg[(size_t)be * D_ + d] = acc * (1.f / K_);
    }
}

// ---------------- residual + layernorm (+optional mask) ----------------
__global__ void add_ln_kernel(const float* __restrict__ add,
                              const float* __restrict__ gamma, const float* __restrict__ beta,
                              const float* __restrict__ mask)
{
    int r = blockIdx.x;
    int t = threadIdx.x;
    __shared__ float red[256];
    float x0 = g_states[(size_t)r*D_ + t]       + add[(size_t)r*D_ + t];
    float x1 = g_states[(size_t)r*D_ + t + 256] + add[(size_t)r*D_ + t + 256];

    red[t] = x0 + x1;
    __syncthreads();
    for (int s = 128; s; s >>= 1) { if (t < s) red[t] += red[t+s]; __syncthreads(); }
    float mu = red[0] * (1.f / D_);
    __syncthreads();

    float d0 = x0 - mu, d1 = x1 - mu;
    red[t] = d0*d0 + d1*d1;
    __syncthreads();
    for (int s = 128; s; s >>= 1) { if (t < s) red[t] += red[t+s]; __syncthreads(); }
    float inv = rsqrtf(red[0] * (1.f / D_) + 1e-5f);

    float mf = mask ? mask[r] : 1.f;
    g_states[(size_t)r*D_ + t]       = (d0 * inv * gamma[t]     + beta[t])     * mf;
    g_states[(size_t)r*D_ + t + 256] = (d1 * inv * gamma[t+256] + beta[t+256]) * mf;
}

// ---------------- memory-token cross attention: one block per (b,h) ----------------
// K/V read once per (b,h); scores matrix in smem; warp-row softmax; tiled PV.
#define ETILE 16
__global__ __launch_bounds__(256) void mem_attn2(const float* __restrict__ edge_mask)
{
    const int b = blockIdx.x >> 3;
    const int h = blockIdx.x & 7;
    const int tid = threadIdx.x;

    __shared__ float Qs[M_][DH_ + 1];     // 32x65
    __shared__ float S[M_][E_];           // 32x256 scores -> probs
    __shared__ float KV[ETILE][DH_ + 1];  // 16x65, reused for K then V

    // load Q slice for this head
    for (int i = tid; i < M_ * DH_; i += 256) {
        int m = i >> 6, d = i & 63;
        Qs[m][d] = g_q[(size_t)m * D_ + h * DH_ + d];
    }

    const float* mk = &edge_mask[(size_t)b * E_];
    const float* kb = &g_k[(size_t)b * E_ * D_ + h * DH_];
    const float* vb = &g_v[(size_t)b * E_ * D_ + h * DH_];
    __syncthreads();

    // scores: tiles of ETILE edges
    for (int et = 0; et < E_ / ETILE; et++) {
        for (int i = tid; i < ETILE * DH_; i += 256) {
            int e = i >> 6, d = i & 63;
            KV[e][d] = kb[(size_t)(et * ETILE + e) * D_ + d];
        }
        __syncthreads();
        #pragma unroll
        for (int p = 0; p < 2; p++) {
            int idx = tid * 2 + p;          // 0..511
            int m = idx >> 4, e = idx & 15;
            float s = 0.f;
            #pragma unroll 8
            for (int d = 0; d < DH_; d++) s += Qs[m][d] * KV[e][d];
            int eg = et * ETILE + e;
            S[m][eg] = (mk[eg] == 0.f) ? -FLT_MAX : s * 0.125f;   // 1/sqrt(64)
        }
        __syncthreads();
    }

    // softmax per memory token: warp w owns rows w*4..w*4+3
    {
        const int warp = tid >> 5, lane = tid & 31;
        for (int r = 0; r < 4; r++) {
            const int m = warp * 4 + r;
            float mx = -FLT_MAX;
            for (int e = lane; e < E_; e += 32) mx = fmaxf(mx, S[m][e]);
            #pragma unroll
            for (int o = 16; o; o >>= 1) mx = fmaxf(mx, __shfl_xor_sync(0xffffffffu, mx, o));
            float sum = 0.f;
            for (int e = lane; e < E_; e += 32) {
                float w = expf(S[m][e] - mx);
                S[m][e] = w;
                sum += w;
            }
            #pragma unroll
            for (int o = 16; o; o >>= 1) sum += __shfl_xor_sync(0xffffffffu, sum, o);
            float inv = 1.f / sum;
            for (int e = lane; e < E_; e += 32) S[m][e] *= inv;
        }
    }
    __syncthreads();

    // PV: thread owns (m = tid>>3, d0 = (tid&7)*8), 8 accumulators
    const int m  = tid >> 3;
    const int d0 = (tid & 7) * 8;
    float acc[8] = {};
    for (int vt = 0; vt < E_ / ETILE; vt++) {
        for (int i = tid; i < ETILE * DH_; i += 256) {
            int e = i >> 6, d = i & 63;
            KV[e][d] = vb[(size_t)(vt * ETILE + e) * D_ + d];
        }
        __syncthreads();
        #pragma unroll
        for (int e = 0; e < ETILE; e++) {
            float w = S[m][vt * ETILE + e];
            #pragma unroll
            for (int j = 0; j < 8; j++) acc[j] += w * KV[e][d0 + j];
        }
        __syncthreads();
    }
    size_t o = (size_t)(b * M_ + m) * D_ + h * DH_ + d0;
    #pragma unroll
    for (int j = 0; j < 8; j++) g_mem[o + j] = acc[j];
}

// ---------------- no-edge handling ----------------
__global__ void noedge_flags(const float* __restrict__ edge_mask)
{
    int b = blockIdx.x;
    __shared__ float red[256];
    red[threadIdx.x] = edge_mask[(size_t)b * E_ + threadIdx.x];
    __syncthreads();
    for (int s = 128; s; s >>= 1) { if (threadIdx.x < s) red[threadIdx.x] += red[threadIdx.x+s]; __syncthreads(); }
    if (threadIdx.x == 0) g_noedge[b] = (red[0] == 0.f) ? 0.f : 1.f;
}

__global__ void apply_noedge()
{
    int i = blockIdx.x * 256 + threadIdx.x;
    int b = i / (M_ * D_);
    g_memo[i] *= g_noedge[b];
}

// ---------------- host launch ----------------
static inline dim3 g64(int Mr, int Nc, int z = 1) {
    return dim3(Nc / 64, (Mr + 63) / 64, z);
}

extern "C" void kernel_launch(void* const* d_in, const int* in_sizes, int n_in,
                              void* d_out, int out_size)
{
    const int*   edge_rel_ids = (const int*)  d_in[0];
    const int*   neigh_ids    = (const int*)  d_in[1];
    const float* edge_mask    = (const float*)d_in[2];
    const float* rel_emb      = (const float*)d_in[3];
    const float* rp_w         = (const float*)d_in[4];
    const float* rp_b         = (const float*)d_in[5];
    const float* ly_vw        = (const float*)d_in[6];
    const float* ly_vb        = (const float*)d_in[7];
    const float* ly_ow        = (const float*)d_in[8];
    const float* ly_ob        = (const float*)d_in[9];
    const float* ly_n1g       = (const float*)d_in[10];
    const float* ly_n1b       = (const float*)d_in[11];
    const float* ly_n2g       = (const float*)d_in[12];
    const float* ly_n2b       = (const float*)d_in[13];
    const float* ly_w1        = (const float*)d_in[14];
    const float* ly_b1        = (const float*)d_in[15];
    const float* ly_w2        = (const float*)d_in[16];
    const float* ly_b2        = (const float*)d_in[17];
    const float* mem_q        = (const float*)d_in[18];
    const float* t_qw         = (const float*)d_in[19];
    const float* t_qb         = (const float*)d_in[20];
    const float* t_kw         = (const float*)d_in[21];
    const float* t_kb         = (const float*)d_in[22];
    const float* t_vw         = (const float*)d_in[23];
    const float* t_vb         = (const float*)d_in[24];
    const float* t_ow         = (const float*)d_in[25];
    const float* t_ob         = (const float*)d_in[26];
    const float* proj_w       = (const float*)d_in[27];
    const float* proj_b       = (const float*)d_in[28];
    float* out = (float*)d_out;

    float *p_relproj, *p_states, *p_agg, *p_tmp1, *p_attn, *p_h, *p_ff;
    float *p_q, *p_k, *p_v, *p_mem, *p_memo;
    cudaGetSymbolAddress((void**)&p_relproj, g_relproj);
    cudaGetSymbolAddress((void**)&p_states,  g_states);
    cudaGetSymbolAddress((void**)&p_agg,     g_agg);
    cudaGetSymbolAddress((void**)&p_tmp1,    g_tmp1);
    cudaGetSymbolAddress((void**)&p_attn,    g_attn);
    cudaGetSymbolAddress((void**)&p_h,       g_h);
    cudaGetSymbolAddress((void**)&p_ff,      g_ff);
    cudaGetSymbolAddress((void**)&p_q,       g_q);
    cudaGetSymbolAddress((void**)&p_k,       g_k);
    cudaGetSymbolAddress((void**)&p_v,       g_v);
    cudaGetSymbolAddress((void**)&p_mem,     g_mem);
    cudaGetSymbolAddress((void**)&p_memo,    g_memo);

    // 1) relation table projection, split-tf32 (near-fp32; feeds top-k ordering)
    gemm64<true><<<g64(R_, D_), 128>>>(rel_emb, rp_w, rp_b, p_relproj,
                                       rp_w, rp_b, p_relproj, R_, D_, RD_, 0);
    rownorm_kernel<<<R_, 256>>>();

    // 2) fused cosine sims / top-8 / mean agg; initializes states = rel_vec
    sims_topk_agg<<<BE_, 256>>>(edge_rel_ids, neigh_ids);

    // 3) relation-context layers (tf32)
    for (int l = 0; l < L_; l++) {
        const float* vw = ly_vw + (size_t)l * D_ * D_;
        const float* vb = ly_vb + (size_t)l * D_;
        const float* ow = ly_ow + (size_t)l * D_ * D_;
        const float* ob = ly_ob + (size_t)l * D_;
        const float* w1 = ly_w1 + (size_t)l * 4 * D_ * D_;
        const float* b1 = ly_b1 + (size_t)l * 4 * D_;
        const float* w2 = ly_w2 + (size_t)l * D_ * 4 * D_;
        const float* b2 = ly_b2 + (size_t)l * D_;

        gemm64<false><<<g64(BE_, D_), 128>>>(p_agg,  vw, vb, p_tmp1, vw, vb, p_tmp1, BE_, D_, D_, 0);
        gemm64<false><<<g64(BE_, D_), 128>>>(p_tmp1, ow, ob, p_attn, ow, ob, p_attn, BE_, D_, D_, 0);
        add_ln_kernel<<<BE_, 256>>>(p_attn, ly_n1g + (size_t)l*D_, ly_n1b + (size_t)l*D_, nullptr);
        gemm64<false><<<g64(BE_, 4*D_), 128>>>(p_states, w1, b1, p_h, w1, b1, p_h, BE_, 4*D_, D_, 1);
        gemm64<false><<<g64(BE_, D_), 128>>>(p_h, w2, b2, p_ff, w2, b2, p_ff, BE_, D_, 4*D_, 0);
        add_ln_kernel<<<BE_, 256>>>(p_ff, ly_n2g + (size_t)l*D_, ly_n2b + (size_t)l*D_, edge_mask);
    }

    // 4) memory tokenizer: q, then batched K/V (gridDim.z = 2)
    gemm64<false><<<g64(M_, D_), 128>>>(mem_q, t_qw, t_qb, p_q, t_qw, t_qb, p_q, M_, D_, D_, 0);
    gemm64<false><<<g64(BE_, D_, 2), 128>>>(p_states, t_kw, t_kb, p_k,
                                            t_vw, t_vb, p_v, BE_, D_, D_, 0);
    mem_attn2<<<B_*HEADS_, 256>>>(edge_mask);
    gemm64<false><<<g64(BM_, D_), 128>>>(p_mem, t_ow, t_ob, p_memo, t_ow, t_ob, p_memo, BM_, D_, D_, 0);
    noedge_flags<<<B_, 256>>>(edge_mask);
    apply_noedge<<<(BM_*D_)/256, 256>>>();

    // 5) final projection to LLM hidden size
    gemm64<false><<<g64(BM_, HLLM_), 128>>>(p_memo, proj_w, proj_b, out,
                                            proj_w, proj_b, out, BM_, HLLM_, D_, 0);
}